// round 8
// baseline (speedup 1.0000x reference)
#include <cuda_runtime.h>
#include <cuda_fp16.h>
#include <math.h>
#include <stdint.h>

#define NN 4096
#define IN_DIM 512
#define OUT_DIM 512
#define HEADS 4
#define DK 128
#define KT 64                    // j-tile
#define S 36                     // smem row stride (32-bit words), banks 4g+tig
#define SW_W (64 * S)            // weight plane words (2304)
#define WH_W (128 * S)           // WhT plane words (4608)
#define BUF_W (SW_W + WH_W)      // one double-buffer plane (6912 words)

// ---------------- scratch ----------------
__device__ float    g_Wh[NN * OUT_DIM];       // 8 MB
__device__ __half   g_WhT2[OUT_DIM * NN];     // 4 MB, [d'][j] fp16
__device__ uint32_t g_Amask[NN * (NN / 32)];  // 2 MB packed adjacency
__device__ float    g_slT[HEADS * NN];
__device__ float    g_srT[HEADS * NN];
__device__ float    g_MT[HEADS * NN];

__device__ __forceinline__ float lrelu(float x) { return x >= 0.f ? x : 0.2f * x; }
__device__ __forceinline__ void mma16816(float* c, uint32_t a0, uint32_t a1,
                                         uint32_t a2, uint32_t a3,
                                         uint32_t b0, uint32_t b1) {
    asm volatile(
        "mma.sync.aligned.m16n8k16.row.col.f32.f16.f16.f32 "
        "{%0,%1,%2,%3}, {%4,%5,%6,%7}, {%8,%9}, {%0,%1,%2,%3};"
        : "+f"(c[0]), "+f"(c[1]), "+f"(c[2]), "+f"(c[3])
        : "r"(a0), "r"(a1), "r"(a2), "r"(a3), "r"(b0), "r"(b1));
}

// ---------------- Kernel A: Wh = H @ W, fused WhT2(fp16) epilogue -----------
__global__ void __launch_bounds__(256) gemm_kernel(const float* __restrict__ H,
                                                   const float* __restrict__ W,
                                                   float* __restrict__ Wh,
                                                   __half* __restrict__ WhT2) {
    __shared__ float As[16][129];
    __shared__ float Bs[16][64];
    const int t = threadIdx.x;
    const int rb = blockIdx.y * 128;
    const int cb = blockIdx.x * 64;
    const int rg = t >> 4;
    const int cg = t & 15;

    float acc[8][4];
#pragma unroll
    for (int u = 0; u < 8; u++)
#pragma unroll
        for (int v = 0; v < 4; v++) acc[u][v] = 0.f;

    for (int kb = 0; kb < IN_DIM; kb += 16) {
#pragma unroll
        for (int i = 0; i < 8; i++) {
            int idx = t + i * 256;
            int m = idx >> 4, kk = idx & 15;
            As[kk][m] = H[(size_t)(rb + m) * IN_DIM + kb + kk];
        }
#pragma unroll
        for (int i = 0; i < 4; i++) {
            int idx = t + i * 256;
            int kk = idx >> 6, c = idx & 63;
            Bs[kk][c] = W[(size_t)(kb + kk) * OUT_DIM + cb + c];
        }
        __syncthreads();
#pragma unroll
        for (int kk = 0; kk < 16; kk++) {
            float a[8], b[4];
#pragma unroll
            for (int u = 0; u < 8; u++) a[u] = As[kk][rg * 8 + u];
#pragma unroll
            for (int v = 0; v < 4; v++) b[v] = Bs[kk][cg * 4 + v];
#pragma unroll
            for (int u = 0; u < 8; u++)
#pragma unroll
                for (int v = 0; v < 4; v++) acc[u][v] = fmaf(a[u], b[v], acc[u][v]);
        }
        __syncthreads();
    }
#pragma unroll
    for (int u = 0; u < 8; u++) {
        float4 o = make_float4(acc[u][0], acc[u][1], acc[u][2], acc[u][3]);
        *reinterpret_cast<float4*>(&Wh[(size_t)(rb + rg * 8 + u) * OUT_DIM + cb + cg * 4]) = o;
    }
    // WhT2[d][j] fp16, per-thread 8 consecutive j -> one uint4
#pragma unroll
    for (int v = 0; v < 4; v++) {
        int d = cb + cg * 4 + v;
        __half2 h2[4];
        h2[0] = __floats2half2_rn(acc[0][v], acc[1][v]);
        h2[1] = __floats2half2_rn(acc[2][v], acc[3][v]);
        h2[2] = __floats2half2_rn(acc[4][v], acc[5][v]);
        h2[3] = __floats2half2_rn(acc[6][v], acc[7][v]);
        *reinterpret_cast<uint4*>(&WhT2[(size_t)d * NN + rb + rg * 8]) =
            *reinterpret_cast<uint4*>(h2);
    }
}

// ---------------- Kernel B: sl/sr (transposed [h][N]) ----------------
__global__ void score_kernel(const float* __restrict__ Wh,
                             const float* __restrict__ al,
                             const float* __restrict__ ar,
                             float* __restrict__ slT, float* __restrict__ srT) {
    int i = blockIdx.x;
    int h = threadIdx.x >> 5;
    int lane = threadIdx.x & 31;
    float4 w = *reinterpret_cast<const float4*>(&Wh[(size_t)i * OUT_DIM + h * DK + lane * 4]);
    float4 l = *reinterpret_cast<const float4*>(&al[h * DK + lane * 4]);
    float4 r = *reinterpret_cast<const float4*>(&ar[h * DK + lane * 4]);
    float s1 = w.x * l.x + w.y * l.y + w.z * l.z + w.w * l.w;
    float s2 = w.x * r.x + w.y * r.y + w.z * r.z + w.w * r.w;
#pragma unroll
    for (int off = 16; off > 0; off >>= 1) {
        s1 += __shfl_xor_sync(0xFFFFFFFFu, s1, off);
        s2 += __shfl_xor_sync(0xFFFFFFFFu, s2, off);
    }
    if (lane == 0) {
        slT[h * NN + i] = s1;
        srT[h * NN + i] = s2;
    }
}

// ---------------- Kernel B2: masked row-max + packed adjacency bitmask ------
__global__ void __launch_bounds__(256) rowmax_kernel(const int* __restrict__ A,
                                                     const float* __restrict__ slT,
                                                     const float* __restrict__ srT,
                                                     float* __restrict__ MT,
                                                     uint32_t* __restrict__ Amask) {
    int i = blockIdx.x;
    int t = threadIdx.x;
    int w = t >> 5, lane = t & 31;
    const int* arow = A + (size_t)i * NN;
    float mx[HEADS];
#pragma unroll
    for (int h = 0; h < HEADS; h++) mx[h] = -INFINITY;
    for (int it = 0; it < NN / 256; it++) {
        int j = it * 256 + t;
        bool edge = arow[j] > 0;
        uint32_t bits = __ballot_sync(0xFFFFFFFFu, edge);
        if (lane == 0) Amask[i * (NN / 32) + it * 8 + w] = bits;
        if (edge || (j == i)) {
#pragma unroll
            for (int h = 0; h < HEADS; h++) mx[h] = fmaxf(mx[h], srT[h * NN + j]);
        }
    }
    __shared__ float red[HEADS][256];
#pragma unroll
    for (int h = 0; h < HEADS; h++) red[h][t] = mx[h];
    __syncthreads();
    for (int s = 128; s > 0; s >>= 1) {
        if (t < s) {
#pragma unroll
            for (int h = 0; h < HEADS; h++)
                red[h][t] = fmaxf(red[h][t], red[h][t + s]);
        }
        __syncthreads();
    }
    if (t < HEADS) {
        float e = slT[t * NN + i] + red[t][0];
        MT[t * NN + i] = lrelu(e);
    }
}

// ---------------- Kernel C: fp16 m16n8k16 masked-softmax aggregation -------
// grid (64, HEADS), 256 threads (8 warps), 2 CTAs/SM. CTA = 64 rows, one head.
// Warp = 16 rows x 64 dims. j tiles of 64, double-buffered, register-pipelined.
__global__ void __launch_bounds__(256, 2) attn_kernel(const uint32_t* __restrict__ Amask,
                                                      const __half* __restrict__ WhT2,
                                                      const float* __restrict__ slT,
                                                      const float* __restrict__ srT,
                                                      const float* __restrict__ MT,
                                                      float* __restrict__ out) {
    extern __shared__ uint32_t dyn[];
    __shared__ float ssl[64], sMx[64], slsum[64];

    const int h = blockIdx.y;
    const int rb = blockIdx.x * 64;
    const int t = threadIdx.x;
    const int wid = t >> 5, lane = t & 31;
    const int g = lane >> 2, tig = lane & 3;
    const int rg = wid >> 1;          // 16-row group 0..3
    const int ch = wid & 1;           // 64-dim half

    if (t < 64) {
        ssl[t] = slT[h * NN + rb + t];
        sMx[t] = MT[h * NN + rb + t];
    }
    __syncthreads();

    // fill mapping (weights): thread -> 1 row x 16 cols
    const int fr = t >> 2;            // row 0..63
    const int fc = (t & 3) * 16;      // col base
    const int gi = rb + fr;
    const float slv = ssl[fr], smv = sMx[fr];
    const float4* srT4 = reinterpret_cast<const float4*>(srT + (size_t)h * NN);
    const float4* WhT4 = reinterpret_cast<const float4*>(WhT2);   // 8 halves per float4

    // fill mapping (WhT tile): 4 float4/thread; flat -> (d, jw)
    //   d = 8*(flat>>6) + (flat&7), jw = (flat>>3)&7  (8-lane phases: same jw, d+0..7)
    float acc[8][4];
#pragma unroll
    for (int nt = 0; nt < 8; nt++)
#pragma unroll
        for (int v = 0; v < 4; v++) acc[nt][v] = 0.f;
    float lacc = 0.f;                 // running lsum partial (row fr, cols fc..fc+15)

    const int arow_a = (rg * 16 + g) * S;
    const int arow_b = arow_a + 8 * S;
    const int nbase = ch * 64;

    uint32_t mraw;
    float4 sr4[4];
    float4 wh[4];

    // ---- prefetch + compute + store tile 0 ----
    {
        mraw = Amask[(size_t)gi * (NN / 32) + (fc >> 5)];
#pragma unroll
        for (int u = 0; u < 4; u++) sr4[u] = srT4[fc / 4 + u];
#pragma unroll
        for (int i = 0; i < 4; i++) {
            int flat = t + i * 256;
            int d = ((flat >> 6) << 3) | (flat & 7);
            int jw = (flat >> 3) & 7;
            wh[i] = WhT4[(size_t)(h * DK + d) * (NN / 8) + jw];
        }
        uint32_t* sw = dyn;
        uint32_t* swh = sw + SW_W;
        uint32_t mb = (fc & 16) ? (mraw >> 16) : mraw;
        const float* srv = reinterpret_cast<const float*>(sr4);
#pragma unroll
        for (int q = 0; q < 2; q++) {
            uint4 pk;
#pragma unroll
            for (int p = 0; p < 4; p++) {
                int uu = q * 8 + p * 2;
                int gj0 = fc + uu, gj1 = gj0 + 1;
                bool al0 = ((mb >> uu) & 1u) || (gi == gj0);
                bool al1 = ((mb >> (uu + 1)) & 1u) || (gi == gj1);
                float w0 = al0 ? __expf(lrelu(slv + srv[uu]) - smv) : 0.f;
                float w1 = al1 ? __expf(lrelu(slv + srv[uu + 1]) - smv) : 0.f;
                __half2 hv = __floats2half2_rn(w0, w1);
                float2 fr2 = __half22float2(hv);
                lacc += fr2.x + fr2.y;
                reinterpret_cast<__half2*>(&pk)[p] = hv;
            }
            *reinterpret_cast<uint4*>(sw + fr * S + (fc >> 1) + q * 4) = pk;
        }
#pragma unroll
        for (int i = 0; i < 4; i++) {
            int flat = t + i * 256;
            int d = ((flat >> 6) << 3) | (flat & 7);
            int jw = (flat >> 3) & 7;
            *reinterpret_cast<float4*>(swh + d * S + jw * 4) = wh[i];
        }
    }
    __syncthreads();

    for (int jt = 0; jt < NN / KT; jt++) {
        // ---- prefetch tile jt+1 (hidden behind MMA) ----
        if (jt + 1 < NN / KT) {
            const int jb = (jt + 1) * KT;
            mraw = Amask[(size_t)gi * (NN / 32) + ((jb + fc) >> 5)];
#pragma unroll
            for (int u = 0; u < 4; u++) sr4[u] = srT4[(jb + fc) / 4 + u];
#pragma unroll
            for (int i = 0; i < 4; i++) {
                int flat = t + i * 256;
                int d = ((flat >> 6) << 3) | (flat & 7);
                int jw = (flat >> 3) & 7;
                wh[i] = WhT4[(size_t)(h * DK + d) * (NN / 8) + (jb >> 3) + jw];
            }
        }

        // ---- mma phase on buffer jt&1: 4 k-chunks of 16 ----
        {
            uint32_t* sw = dyn + (jt & 1) * BUF_W;
            uint32_t* swh = sw + SW_W;
#pragma unroll
            for (int kc = 0; kc < 4; kc++) {
                const int k0 = kc * 8 + tig;
                uint32_t a0 = sw[arow_a + k0];
                uint32_t a2 = sw[arow_a + k0 + 4];
                uint32_t a1 = sw[arow_b + k0];
                uint32_t a3 = sw[arow_b + k0 + 4];
#pragma unroll
                for (int nt = 0; nt < 8; nt++) {
                    uint32_t b0 = swh[(nbase + nt * 8 + g) * S + k0];
                    uint32_t b1 = swh[(nbase + nt * 8 + g) * S + k0 + 4];
                    mma16816(acc[nt], a0, a1, a2, a3, b0, b1);
                }
            }
        }

        // ---- store tile jt+1 into buffer (jt+1)&1 ----
        if (jt + 1 < NN / KT) {
            const int jb = (jt + 1) * KT;
            uint32_t* sw = dyn + ((jt + 1) & 1) * BUF_W;
            uint32_t* swh = sw + SW_W;
            uint32_t mb = (fc & 16) ? (mraw >> 16) : mraw;
            const float* srv = reinterpret_cast<const float*>(sr4);
#pragma unroll
            for (int q = 0; q < 2; q++) {
                uint4 pk;
#pragma unroll
                for (int p = 0; p < 4; p++) {
                    int uu = q * 8 + p * 2;
                    int gj0 = jb + fc + uu, gj1 = gj0 + 1;
                    bool al0 = ((mb >> uu) & 1u) || (gi == gj0);
                    bool al1 = ((mb >> (uu + 1)) & 1u) || (gi == gj1);
                    float w0 = al0 ? __expf(lrelu(slv + srv[uu]) - smv) : 0.f;
                    float w1 = al1 ? __expf(lrelu(slv + srv[uu + 1]) - smv) : 0.f;
                    __half2 hv = __floats2half2_rn(w0, w1);
                    float2 fr2 = __half22float2(hv);
                    lacc += fr2.x + fr2.y;
                    reinterpret_cast<__half2*>(&pk)[p] = hv;
                }
                *reinterpret_cast<uint4*>(sw + fr * S + (fc >> 1) + q * 4) = pk;
            }
#pragma unroll
            for (int i = 0; i < 4; i++) {
                int flat = t + i * 256;
                int d = ((flat >> 6) << 3) | (flat & 7);
                int jw = (flat >> 3) & 7;
                *reinterpret_cast<float4*>(swh + d * S + jw * 4) = wh[i];
            }
        }
        __syncthreads();
    }

    // ---- lsum: quad-reduce (lanes of a quad share row fr) ----
    lacc += __shfl_xor_sync(0xFFFFFFFFu, lacc, 1);
    lacc += __shfl_xor_sync(0xFFFFFFFFu, lacc, 2);
    if ((t & 3) == 0) slsum[fr] = lacc;
    __syncthreads();

    // ---- epilogue: normalize + ELU, float2 stores ----
    const int r0l = rg * 16 + g;
    const int r1l = r0l + 8;
    const float inv0 = 1.f / slsum[r0l];
    const float inv1 = 1.f / slsum[r1l];
    const int row0 = rb + r0l, row1 = rb + r1l;
#pragma unroll
    for (int nt = 0; nt < 8; nt++) {
        int col = h * DK + nbase + nt * 8 + 2 * tig;
        float x0 = acc[nt][0] * inv0, x1 = acc[nt][1] * inv0;
        float y0 = acc[nt][2] * inv1, y1 = acc[nt][3] * inv1;
        float2 o0, o1;
        o0.x = x0 > 0.f ? x0 : (__expf(x0) - 1.f);
        o0.y = x1 > 0.f ? x1 : (__expf(x1) - 1.f);
        o1.x = y0 > 0.f ? y0 : (__expf(y0) - 1.f);
        o1.y = y1 > 0.f ? y1 : (__expf(y1) - 1.f);
        *reinterpret_cast<float2*>(&out[(size_t)row0 * OUT_DIM + col]) = o0;
        *reinterpret_cast<float2*>(&out[(size_t)row1 * OUT_DIM + col]) = o1;
    }
}

// ---------------- launch ----------------
extern "C" void kernel_launch(void* const* d_in, const int* in_sizes, int n_in,
                              void* d_out, int out_size) {
    const float* H  = (const float*)d_in[0];
    const int*   A  = (const int*)  d_in[1];
    const float* W  = (const float*)d_in[2];
    const float* al = (const float*)d_in[3];
    const float* ar = (const float*)d_in[4];
    float* out = (float*)d_out;

    float*    Wh;    cudaGetSymbolAddress((void**)&Wh,    g_Wh);
    __half*   WhT2;  cudaGetSymbolAddress((void**)&WhT2,  g_WhT2);
    uint32_t* Amask; cudaGetSymbolAddress((void**)&Amask, g_Amask);
    float*    slT;   cudaGetSymbolAddress((void**)&slT,   g_slT);
    float*    srT;   cudaGetSymbolAddress((void**)&srT,   g_srT);
    float*    MT;    cudaGetSymbolAddress((void**)&MT,    g_MT);

    dim3 gA(OUT_DIM / 64, NN / 128);
    gemm_kernel<<<gA, 256>>>(H, W, Wh, WhT2);

    score_kernel<<<NN, 128>>>(Wh, al, ar, slT, srT);

    rowmax_kernel<<<NN, 256>>>(A, slT, srT, MT, Amask);

    const int dyn_bytes = 2 * BUF_W * 4;   // 55296
    cudaFuncSetAttribute(attn_kernel, cudaFuncAttributeMaxDynamicSharedMemorySize, dyn_bytes);
    dim3 gC(NN / 64, HEADS);
    attn_kernel<<<gC, 256, dyn_bytes>>>(Amask, WhT2, slT, srT, MT, out);
}

// round 9
// speedup vs baseline: 2.4018x; 2.4018x over previous
#include <cuda_runtime.h>
#include <cuda_fp16.h>
#include <math.h>
#include <stdint.h>

#define NN 4096
#define IN_DIM 512
#define OUT_DIM 512
#define HEADS 4
#define DK 128
#define KT 64                    // j-tile
#define S 36                     // smem row stride (words)
#define WH_W (128 * S)           // WhT plane words (4608)
#define LOG2E 1.4426950408889634f

// ---------------- scratch ----------------
__device__ float    g_Wh[NN * OUT_DIM];       // 8 MB
__device__ __half   g_WhT2[OUT_DIM * NN];     // 4 MB, [d'][j] fp16
__device__ uint32_t g_Amask[NN * (NN / 32)];  // 2 MB packed adjacency
__device__ float    g_slT[HEADS * NN];        // prescaled by LOG2E
__device__ float    g_srT[HEADS * NN];        // prescaled by LOG2E
__device__ float    g_MT[HEADS * NN];         // prescaled (derived)

__device__ __forceinline__ float lrelu(float x) { return fmaxf(x, 0.2f * x); }
__device__ __forceinline__ float ex2(float x) {
    float r;
    asm("ex2.approx.ftz.f32 %0, %1;" : "=f"(r) : "f"(x));
    return r;
}
__device__ __forceinline__ uint32_t packh2(float lo, float hi) {
    __half2 h = __floats2half2_rn(lo, hi);
    return *reinterpret_cast<uint32_t*>(&h);
}
__device__ __forceinline__ void mma16816(float* c, uint32_t a0, uint32_t a1,
                                         uint32_t a2, uint32_t a3,
                                         uint32_t b0, uint32_t b1) {
    asm volatile(
        "mma.sync.aligned.m16n8k16.row.col.f32.f16.f16.f32 "
        "{%0,%1,%2,%3}, {%4,%5,%6,%7}, {%8,%9}, {%0,%1,%2,%3};"
        : "+f"(c[0]), "+f"(c[1]), "+f"(c[2]), "+f"(c[3])
        : "r"(a0), "r"(a1), "r"(a2), "r"(a3), "r"(b0), "r"(b1));
}
__device__ __forceinline__ uint64_t merge_mask(uint2 m, int gi, int jb) {
    uint64_t M = (uint64_t)m.x | ((uint64_t)m.y << 32);
    unsigned sc = (unsigned)(gi - jb);
    if (sc < 64u) M |= (1ull << sc);
    return M;
}

// ---------------- Kernel A: Wh = H @ W, fused WhT2(fp16) epilogue -----------
__global__ void __launch_bounds__(256) gemm_kernel(const float* __restrict__ H,
                                                   const float* __restrict__ W,
                                                   float* __restrict__ Wh,
                                                   __half* __restrict__ WhT2) {
    __shared__ float As[16][129];
    __shared__ float Bs[16][64];
    const int t = threadIdx.x;
    const int rb = blockIdx.y * 128;
    const int cb = blockIdx.x * 64;
    const int rg = t >> 4;
    const int cg = t & 15;

    float acc[8][4];
#pragma unroll
    for (int u = 0; u < 8; u++)
#pragma unroll
        for (int v = 0; v < 4; v++) acc[u][v] = 0.f;

    for (int kb = 0; kb < IN_DIM; kb += 16) {
#pragma unroll
        for (int i = 0; i < 8; i++) {
            int idx = t + i * 256;
            int m = idx >> 4, kk = idx & 15;
            As[kk][m] = H[(size_t)(rb + m) * IN_DIM + kb + kk];
        }
#pragma unroll
        for (int i = 0; i < 4; i++) {
            int idx = t + i * 256;
            int kk = idx >> 6, c = idx & 63;
            Bs[kk][c] = W[(size_t)(kb + kk) * OUT_DIM + cb + c];
        }
        __syncthreads();
#pragma unroll
        for (int kk = 0; kk < 16; kk++) {
            float a[8], b[4];
#pragma unroll
            for (int u = 0; u < 8; u++) a[u] = As[kk][rg * 8 + u];
#pragma unroll
            for (int v = 0; v < 4; v++) b[v] = Bs[kk][cg * 4 + v];
#pragma unroll
            for (int u = 0; u < 8; u++)
#pragma unroll
                for (int v = 0; v < 4; v++) acc[u][v] = fmaf(a[u], b[v], acc[u][v]);
        }
        __syncthreads();
    }
#pragma unroll
    for (int u = 0; u < 8; u++) {
        float4 o = make_float4(acc[u][0], acc[u][1], acc[u][2], acc[u][3]);
        *reinterpret_cast<float4*>(&Wh[(size_t)(rb + rg * 8 + u) * OUT_DIM + cb + cg * 4]) = o;
    }
#pragma unroll
    for (int v = 0; v < 4; v++) {
        int d = cb + cg * 4 + v;
        __half2 h2[4];
        h2[0] = __floats2half2_rn(acc[0][v], acc[1][v]);
        h2[1] = __floats2half2_rn(acc[2][v], acc[3][v]);
        h2[2] = __floats2half2_rn(acc[4][v], acc[5][v]);
        h2[3] = __floats2half2_rn(acc[6][v], acc[7][v]);
        *reinterpret_cast<uint4*>(&WhT2[(size_t)d * NN + rb + rg * 8]) =
            *reinterpret_cast<uint4*>(h2);
    }
}

// ---------------- Kernel B: sl/sr (transposed [h][N], prescaled) ------------
__global__ void score_kernel(const float* __restrict__ Wh,
                             const float* __restrict__ al,
                             const float* __restrict__ ar,
                             float* __restrict__ slT, float* __restrict__ srT) {
    int i = blockIdx.x;
    int h = threadIdx.x >> 5;
    int lane = threadIdx.x & 31;
    float4 w = *reinterpret_cast<const float4*>(&Wh[(size_t)i * OUT_DIM + h * DK + lane * 4]);
    float4 l = *reinterpret_cast<const float4*>(&al[h * DK + lane * 4]);
    float4 r = *reinterpret_cast<const float4*>(&ar[h * DK + lane * 4]);
    float s1 = w.x * l.x + w.y * l.y + w.z * l.z + w.w * l.w;
    float s2 = w.x * r.x + w.y * r.y + w.z * r.z + w.w * r.w;
#pragma unroll
    for (int off = 16; off > 0; off >>= 1) {
        s1 += __shfl_xor_sync(0xFFFFFFFFu, s1, off);
        s2 += __shfl_xor_sync(0xFFFFFFFFu, s2, off);
    }
    if (lane == 0) {
        slT[h * NN + i] = s1 * LOG2E;
        srT[h * NN + i] = s2 * LOG2E;
    }
}

// ---------------- Kernel B2: masked row-max + packed adjacency bitmask ------
__global__ void __launch_bounds__(256) rowmax_kernel(const int* __restrict__ A,
                                                     const float* __restrict__ slT,
                                                     const float* __restrict__ srT,
                                                     float* __restrict__ MT,
                                                     uint32_t* __restrict__ Amask) {
    int i = blockIdx.x;
    int t = threadIdx.x;
    int w = t >> 5, lane = t & 31;
    const int* arow = A + (size_t)i * NN;
    float mx[HEADS];
#pragma unroll
    for (int h = 0; h < HEADS; h++) mx[h] = -INFINITY;
    for (int it = 0; it < NN / 256; it++) {
        int j = it * 256 + t;
        bool edge = arow[j] > 0;
        uint32_t bits = __ballot_sync(0xFFFFFFFFu, edge);
        if (lane == 0) Amask[i * (NN / 32) + it * 8 + w] = bits;
        if (edge || (j == i)) {
#pragma unroll
            for (int h = 0; h < HEADS; h++) mx[h] = fmaxf(mx[h], srT[h * NN + j]);
        }
    }
    __shared__ float red[HEADS][256];
#pragma unroll
    for (int h = 0; h < HEADS; h++) red[h][t] = mx[h];
    __syncthreads();
    for (int s = 128; s > 0; s >>= 1) {
        if (t < s) {
#pragma unroll
            for (int h = 0; h < HEADS; h++)
                red[h][t] = fmaxf(red[h][t], red[h][t + s]);
        }
        __syncthreads();
    }
    if (t < HEADS) {
        float e = slT[t * NN + i] + red[t][0];
        MT[t * NN + i] = lrelu(e);
    }
}

// ---------------- Kernel C: fp16 MMA, in-register A-fragment weights --------
// grid (64, HEADS), 256 threads (8 warps), 2 CTAs/SM. CTA = 64 rows, one head.
// Warp = 16 rows x 64 dims. Only the WhT tile lives in (double-buffered) smem.
__global__ void __launch_bounds__(256, 2) attn_kernel(const uint32_t* __restrict__ Amask,
                                                      const __half* __restrict__ WhT2,
                                                      const float* __restrict__ slT,
                                                      const float* __restrict__ srT,
                                                      const float* __restrict__ MT,
                                                      float* __restrict__ out) {
    extern __shared__ uint32_t dyn[];          // 2 x WH_W
    __shared__ float ssr[NN];                  // full srT row for this head
    __shared__ float ssl[64], sMx[64], slsum[64];

    const int h = blockIdx.y;
    const int rb = blockIdx.x * 64;
    const int t = threadIdx.x;
    const int wid = t >> 5, lane = t & 31;
    const int g = lane >> 2, tig = lane & 3;
    const int rg = wid >> 1;          // 16-row group 0..3
    const int ch = wid & 1;           // 64-dim half

    // persistent loads
    {
        const float4* s4 = reinterpret_cast<const float4*>(srT + (size_t)h * NN);
#pragma unroll
        for (int i = 0; i < 4; i++) {
            int idx = t + i * 256;
            reinterpret_cast<float4*>(ssr)[idx] = s4[idx];
        }
    }
    if (t < 64) {
        ssl[t] = slT[h * NN + rb + t];
        sMx[t] = MT[h * NN + rb + t];
    }
    __syncthreads();

    const int r0l = rg * 16 + g, r1l = r0l + 8;
    const int gi0 = rb + r0l, gi1 = rb + r1l;
    const float slv0 = ssl[r0l], smv0 = sMx[r0l];
    const float slv1 = ssl[r1l], smv1 = sMx[r1l];
    const int nbase = ch * 64;
    const uint4* WhT4 = reinterpret_cast<const uint4*>(WhT2);

    float acc[8][4];
#pragma unroll
    for (int nt = 0; nt < 8; nt++)
#pragma unroll
        for (int v = 0; v < 4; v++) acc[nt][v] = 0.f;
    float lacc0 = 0.f, lacc1 = 0.f;

    uint64_t M0, M1;
    uint4 wh[4];
    uint2 nm0, nm1;

    // ---- prologue: masks + WhT for tile 0 ----
    {
        nm0 = *reinterpret_cast<const uint2*>(Amask + (size_t)gi0 * (NN / 32));
        nm1 = *reinterpret_cast<const uint2*>(Amask + (size_t)gi1 * (NN / 32));
        M0 = merge_mask(nm0, gi0, 0);
        M1 = merge_mask(nm1, gi1, 0);
        uint32_t* swh = dyn;
#pragma unroll
        for (int i = 0; i < 4; i++) {
            int flat = t + i * 256;
            int d = flat >> 3, jw = flat & 7;
            wh[i] = WhT4[(size_t)(h * DK + d) * (NN / 8) + jw];
        }
#pragma unroll
        for (int i = 0; i < 4; i++) {
            int flat = t + i * 256;
            int d = flat >> 3, jw = flat & 7;
            *reinterpret_cast<uint4*>(swh + d * S + jw * 4) = wh[i];
        }
    }
    __syncthreads();

    for (int jt = 0; jt < NN / KT; jt++) {
        const int jb = jt * KT;
        // ---- prefetch tile jt+1 (globals only; hidden behind MMA) ----
        if (jt + 1 < NN / KT) {
            const int jbn = jb + KT;
            nm0 = *reinterpret_cast<const uint2*>(Amask + (size_t)gi0 * (NN / 32) + 2 * (jt + 1));
            nm1 = *reinterpret_cast<const uint2*>(Amask + (size_t)gi1 * (NN / 32) + 2 * (jt + 1));
#pragma unroll
            for (int i = 0; i < 4; i++) {
                int flat = t + i * 256;
                int d = flat >> 3, jw = flat & 7;
                wh[i] = WhT4[(size_t)(h * DK + d) * (NN / 8) + (jbn >> 3) + jw];
            }
        }

        // ---- MMA phase: weights in-register + B from smem ----
        {
            const uint32_t* swh = dyn + (jt & 1) * WH_W;
#pragma unroll
            for (int kc = 0; kc < 4; kc++) {
                const int c0 = kc * 16 + 2 * tig;
                float2 srA = *reinterpret_cast<const float2*>(&ssr[jb + c0]);
                float2 srB = *reinterpret_cast<const float2*>(&ssr[jb + c0 + 8]);
                uint32_t sh0 = (uint32_t)(M0 >> c0);
                uint32_t sh1 = (uint32_t)(M1 >> c0);
                float w00 = (sh0 & 1u)        ? ex2(lrelu(slv0 + srA.x) - smv0) : 0.f;
                float w01 = ((sh0 >> 1) & 1u) ? ex2(lrelu(slv0 + srA.y) - smv0) : 0.f;
                float w02 = ((sh0 >> 8) & 1u) ? ex2(lrelu(slv0 + srB.x) - smv0) : 0.f;
                float w03 = ((sh0 >> 9) & 1u) ? ex2(lrelu(slv0 + srB.y) - smv0) : 0.f;
                float w10 = (sh1 & 1u)        ? ex2(lrelu(slv1 + srA.x) - smv1) : 0.f;
                float w11 = ((sh1 >> 1) & 1u) ? ex2(lrelu(slv1 + srA.y) - smv1) : 0.f;
                float w12 = ((sh1 >> 8) & 1u) ? ex2(lrelu(slv1 + srB.x) - smv1) : 0.f;
                float w13 = ((sh1 >> 9) & 1u) ? ex2(lrelu(slv1 + srB.y) - smv1) : 0.f;
                lacc0 += (w00 + w01) + (w02 + w03);
                lacc1 += (w10 + w11) + (w12 + w13);
                uint32_t a0 = packh2(w00, w01);
                uint32_t a2 = packh2(w02, w03);
                uint32_t a1 = packh2(w10, w11);
                uint32_t a3 = packh2(w12, w13);
                const int k0 = kc * 8 + tig;
#pragma unroll
                for (int nt = 0; nt < 8; nt++) {
                    uint32_t b0 = swh[(nbase + nt * 8 + g) * S + k0];
                    uint32_t b1 = swh[(nbase + nt * 8 + g) * S + k0 + 4];
                    mma16816(acc[nt], a0, a1, a2, a3, b0, b1);
                }
            }
        }

        // ---- store tile jt+1 + advance masks ----
        if (jt + 1 < NN / KT) {
            const int jbn = jb + KT;
            uint32_t* swh = dyn + ((jt + 1) & 1) * WH_W;
#pragma unroll
            for (int i = 0; i < 4; i++) {
                int flat = t + i * 256;
                int d = flat >> 3, jw = flat & 7;
                *reinterpret_cast<uint4*>(swh + d * S + jw * 4) = wh[i];
            }
            M0 = merge_mask(nm0, gi0, jbn);
            M1 = merge_mask(nm1, gi1, jbn);
        }
        __syncthreads();
    }

    // ---- lsum: quad-reduce; ch==0 warps own the rows ----
    lacc0 += __shfl_xor_sync(0xFFFFFFFFu, lacc0, 1);
    lacc0 += __shfl_xor_sync(0xFFFFFFFFu, lacc0, 2);
    lacc1 += __shfl_xor_sync(0xFFFFFFFFu, lacc1, 1);
    lacc1 += __shfl_xor_sync(0xFFFFFFFFu, lacc1, 2);
    if (ch == 0 && tig == 0) {
        slsum[r0l] = lacc0;
        slsum[r1l] = lacc1;
    }
    __syncthreads();

    // ---- epilogue: normalize + ELU, float2 stores ----
    const float inv0 = 1.f / slsum[r0l];
    const float inv1 = 1.f / slsum[r1l];
    const int row0 = rb + r0l, row1 = rb + r1l;
#pragma unroll
    for (int nt = 0; nt < 8; nt++) {
        int col = h * DK + nbase + nt * 8 + 2 * tig;
        float x0 = acc[nt][0] * inv0, x1 = acc[nt][1] * inv0;
        float y0 = acc[nt][2] * inv1, y1 = acc[nt][3] * inv1;
        float2 o0, o1;
        o0.x = x0 > 0.f ? x0 : (__expf(x0) - 1.f);
        o0.y = x1 > 0.f ? x1 : (__expf(x1) - 1.f);
        o1.x = y0 > 0.f ? y0 : (__expf(y0) - 1.f);
        o1.y = y1 > 0.f ? y1 : (__expf(y1) - 1.f);
        *reinterpret_cast<float2*>(&out[(size_t)row0 * OUT_DIM + col]) = o0;
        *reinterpret_cast<float2*>(&out[(size_t)row1 * OUT_DIM + col]) = o1;
    }
}

// ---------------- launch ----------------
extern "C" void kernel_launch(void* const* d_in, const int* in_sizes, int n_in,
                              void* d_out, int out_size) {
    const float* H  = (const float*)d_in[0];
    const int*   A  = (const int*)  d_in[1];
    const float* W  = (const float*)d_in[2];
    const float* al = (const float*)d_in[3];
    const float* ar = (const float*)d_in[4];
    float* out = (float*)d_out;

    float*    Wh;    cudaGetSymbolAddress((void**)&Wh,    g_Wh);
    __half*   WhT2;  cudaGetSymbolAddress((void**)&WhT2,  g_WhT2);
    uint32_t* Amask; cudaGetSymbolAddress((void**)&Amask, g_Amask);
    float*    slT;   cudaGetSymbolAddress((void**)&slT,   g_slT);
    float*    srT;   cudaGetSymbolAddress((void**)&srT,   g_srT);
    float*    MT;    cudaGetSymbolAddress((void**)&MT,    g_MT);

    dim3 gA(OUT_DIM / 64, NN / 128);
    gemm_kernel<<<gA, 256>>>(H, W, Wh, WhT2);

    score_kernel<<<NN, 128>>>(Wh, al, ar, slT, srT);

    rowmax_kernel<<<NN, 256>>>(A, slT, srT, MT, Amask);

    const int dyn_bytes = 2 * WH_W * 4;   // 36864
    cudaFuncSetAttribute(attn_kernel, cudaFuncAttributeMaxDynamicSharedMemorySize, dyn_bytes);
    dim3 gC(NN / 64, HEADS);
    attn_kernel<<<gC, 256, dyn_bytes>>>(Amask, WhT2, slT, srT, MT, out);
}

// round 10
// speedup vs baseline: 2.4973x; 1.0398x over previous
#include <cuda_runtime.h>
#include <cuda_fp16.h>
#include <math.h>
#include <stdint.h>

#define NN 4096
#define IN_DIM 512
#define OUT_DIM 512
#define HEADS 4
#define DK 128
#define KT 64
#define S 36                       // swh row stride (words) = 144B
#define WH_W (128 * S)             // one swh buffer (words)
#define WH_BYTES (WH_W * 4)        // 18432
#define FRAG_W (16 * 32 * 4)       // one frag buffer (words) = 8KB
#define LOG2E 1.4426950408889634f

// ---------------- scratch ----------------
__device__ float    g_Wh[NN * OUT_DIM];
__device__ __half   g_WhT2[OUT_DIM * NN];     // [d'][j] fp16
__device__ uint32_t g_Amask[NN * (NN / 32)];
__device__ float    g_slT[HEADS * NN];        // *LOG2E
__device__ float    g_srT[HEADS * NN];        // *LOG2E (fp32, for rowmax)
__device__ __half   g_srT2[HEADS * NN];       // *LOG2E (fp16, for attn)
__device__ float    g_MT[HEADS * NN];         // *LOG2E (derived)

__device__ __forceinline__ float lrelu(float x) { return fmaxf(x, 0.2f * x); }

__device__ __forceinline__ void mma16816(float* c, uint32_t a0, uint32_t a1,
                                         uint32_t a2, uint32_t a3,
                                         uint32_t b0, uint32_t b1) {
    asm volatile(
        "mma.sync.aligned.m16n8k16.row.col.f32.f16.f16.f32 "
        "{%0,%1,%2,%3}, {%4,%5,%6,%7}, {%8,%9}, {%0,%1,%2,%3};"
        : "+f"(c[0]), "+f"(c[1]), "+f"(c[2]), "+f"(c[3])
        : "r"(a0), "r"(a1), "r"(a2), "r"(a3), "r"(b0), "r"(b1));
}
__device__ __forceinline__ void ldsm4(uint32_t& r0, uint32_t& r1,
                                      uint32_t& r2, uint32_t& r3, uint32_t addr) {
    asm volatile("ldmatrix.sync.aligned.m8n8.x4.shared.b16 {%0,%1,%2,%3}, [%4];"
                 : "=r"(r0), "=r"(r1), "=r"(r2), "=r"(r3) : "r"(addr));
}
__device__ __forceinline__ uint64_t merge_mask(uint2 m, int gi, int jb) {
    uint64_t M = (uint64_t)m.x | ((uint64_t)m.y << 32);
    unsigned sc = (unsigned)(gi - jb);
    if (sc < 64u) M |= (1ull << sc);
    return M;
}
// half2 weight: 2^( max(e,0.2e) - m ) masked, packed as A-frag register
__device__ __forceinline__ uint32_t wcalc(__half2 sl2, __half2 nm2, __half2 sr2,
                                          uint32_t b0, uint32_t b1) {
    __half2 e = __hadd2(sl2, sr2);
    __half2 t = __hmul2(e, __float2half2_rn(0.2f));
    e = __hmax2(e, t);
    e = __hadd2(e, nm2);
    __half2 w = h2exp2(e);
    uint32_t m = (b0 ? 0x3C00u : 0u) | (b1 ? 0x3C000000u : 0u);
    __half2 mh = *reinterpret_cast<__half2*>(&m);
    w = __hmul2(w, mh);
    return *reinterpret_cast<uint32_t*>(&w);
}

// ---------------- Kernel A: Wh = H @ W, fused WhT2(fp16) epilogue -----------
__global__ void __launch_bounds__(256) gemm_kernel(const float* __restrict__ H,
                                                   const float* __restrict__ W,
                                                   float* __restrict__ Wh,
                                                   __half* __restrict__ WhT2) {
    __shared__ float As[16][129];
    __shared__ float Bs[16][64];
    const int t = threadIdx.x;
    const int rb = blockIdx.y * 128;
    const int cb = blockIdx.x * 64;
    const int rg = t >> 4;
    const int cg = t & 15;

    float acc[8][4];
#pragma unroll
    for (int u = 0; u < 8; u++)
#pragma unroll
        for (int v = 0; v < 4; v++) acc[u][v] = 0.f;

    for (int kb = 0; kb < IN_DIM; kb += 16) {
#pragma unroll
        for (int i = 0; i < 8; i++) {
            int idx = t + i * 256;
            int m = idx >> 4, kk = idx & 15;
            As[kk][m] = H[(size_t)(rb + m) * IN_DIM + kb + kk];
        }
#pragma unroll
        for (int i = 0; i < 4; i++) {
            int idx = t + i * 256;
            int kk = idx >> 6, c = idx & 63;
            Bs[kk][c] = W[(size_t)(kb + kk) * OUT_DIM + cb + c];
        }
        __syncthreads();
#pragma unroll
        for (int kk = 0; kk < 16; kk++) {
            float a[8], b[4];
#pragma unroll
            for (int u = 0; u < 8; u++) a[u] = As[kk][rg * 8 + u];
#pragma unroll
            for (int v = 0; v < 4; v++) b[v] = Bs[kk][cg * 4 + v];
#pragma unroll
            for (int u = 0; u < 8; u++)
#pragma unroll
                for (int v = 0; v < 4; v++) acc[u][v] = fmaf(a[u], b[v], acc[u][v]);
        }
        __syncthreads();
    }
#pragma unroll
    for (int u = 0; u < 8; u++) {
        float4 o = make_float4(acc[u][0], acc[u][1], acc[u][2], acc[u][3]);
        *reinterpret_cast<float4*>(&Wh[(size_t)(rb + rg * 8 + u) * OUT_DIM + cb + cg * 4]) = o;
    }
#pragma unroll
    for (int v = 0; v < 4; v++) {
        int d = cb + cg * 4 + v;
        __half2 h2[4];
        h2[0] = __floats2half2_rn(acc[0][v], acc[1][v]);
        h2[1] = __floats2half2_rn(acc[2][v], acc[3][v]);
        h2[2] = __floats2half2_rn(acc[4][v], acc[5][v]);
        h2[3] = __floats2half2_rn(acc[6][v], acc[7][v]);
        *reinterpret_cast<uint4*>(&WhT2[(size_t)d * NN + rb + rg * 8]) =
            *reinterpret_cast<uint4*>(h2);
    }
}

// ---------------- Kernel B: sl/sr, prescaled; fp32 + fp16 copies ------------
__global__ void score_kernel(const float* __restrict__ Wh,
                             const float* __restrict__ al,
                             const float* __restrict__ ar,
                             float* __restrict__ slT, float* __restrict__ srT,
                             __half* __restrict__ srT2) {
    int i = blockIdx.x;
    int h = threadIdx.x >> 5;
    int lane = threadIdx.x & 31;
    float4 w = *reinterpret_cast<const float4*>(&Wh[(size_t)i * OUT_DIM + h * DK + lane * 4]);
    float4 l = *reinterpret_cast<const float4*>(&al[h * DK + lane * 4]);
    float4 r = *reinterpret_cast<const float4*>(&ar[h * DK + lane * 4]);
    float s1 = w.x * l.x + w.y * l.y + w.z * l.z + w.w * l.w;
    float s2 = w.x * r.x + w.y * r.y + w.z * r.z + w.w * r.w;
#pragma unroll
    for (int off = 16; off > 0; off >>= 1) {
        s1 += __shfl_xor_sync(0xFFFFFFFFu, s1, off);
        s2 += __shfl_xor_sync(0xFFFFFFFFu, s2, off);
    }
    if (lane == 0) {
        slT[h * NN + i] = s1 * LOG2E;
        srT[h * NN + i] = s2 * LOG2E;
        srT2[h * NN + i] = __float2half_rn(s2 * LOG2E);
    }
}

// ---------------- Kernel B2: masked row-max + packed adjacency --------------
__global__ void __launch_bounds__(256) rowmax_kernel(const int* __restrict__ A,
                                                     const float* __restrict__ slT,
                                                     const float* __restrict__ srT,
                                                     float* __restrict__ MT,
                                                     uint32_t* __restrict__ Amask) {
    int i = blockIdx.x;
    int t = threadIdx.x;
    int w = t >> 5, lane = t & 31;
    const int* arow = A + (size_t)i * NN;
    float mx[HEADS];
#pragma unroll
    for (int h = 0; h < HEADS; h++) mx[h] = -INFINITY;
    for (int it = 0; it < NN / 256; it++) {
        int j = it * 256 + t;
        bool edge = arow[j] > 0;
        uint32_t bits = __ballot_sync(0xFFFFFFFFu, edge);
        if (lane == 0) Amask[i * (NN / 32) + it * 8 + w] = bits;
        if (edge || (j == i)) {
#pragma unroll
            for (int h = 0; h < HEADS; h++) mx[h] = fmaxf(mx[h], srT[h * NN + j]);
        }
    }
    __shared__ float red[HEADS][256];
#pragma unroll
    for (int h = 0; h < HEADS; h++) red[h][t] = mx[h];
    __syncthreads();
    for (int s = 128; s > 0; s >>= 1) {
        if (t < s) {
#pragma unroll
            for (int h = 0; h < HEADS; h++)
                red[h][t] = fmaxf(red[h][t], red[h][t + s]);
        }
        __syncthreads();
    }
    if (t < HEADS) {
        float e = slT[t * NN + i] + red[t][0];
        MT[t * NN + i] = lrelu(e);
    }
}

// ---------------- Kernel C: fp16 MMA, shared frags + ldmatrix + ones-lsum ---
// grid (64, HEADS), 256 threads (8 warps), 2 CTAs/SM. CTA = 64 rows, one head.
__global__ void __launch_bounds__(256, 2) attn_kernel(const uint32_t* __restrict__ Amask,
                                                      const __half* __restrict__ WhT2,
                                                      const float* __restrict__ slT,
                                                      const __half* __restrict__ srT2,
                                                      const float* __restrict__ MT,
                                                      float* __restrict__ out) {
    extern __shared__ uint32_t dyn[];             // 2 x WH_W (swh buffers)
    __shared__ __align__(16) __half ssr[NN];      // 8 KB fp16 srT row
    __shared__ __align__(16) uint32_t sfrag[2 * FRAG_W];  // 16 KB A-frag buffers
    __shared__ float ssl[64], sMx[64];

    const int h = blockIdx.y;
    const int rb = blockIdx.x * 64;
    const int t = threadIdx.x;
    const int wid = t >> 5, lane = t & 31;
    const int g = lane >> 2, tig = lane & 3;
    const int rg = wid >> 1;          // 16-row group 0..3
    const int ch = wid & 1;           // 64-dim half
    const int nbase = ch * 64;

    // persistent loads
    {
        const uint4* s4 = reinterpret_cast<const uint4*>(srT2 + (size_t)h * NN);
#pragma unroll
        for (int i = 0; i < 2; i++) {
            int idx = t + i * 256;
            reinterpret_cast<uint4*>(ssr)[idx] = s4[idx];
        }
    }
    if (t < 64) {
        ssl[t] = slT[h * NN + rb + t];
        sMx[t] = MT[h * NN + rb + t];
    }
    __syncthreads();

    const int r0l = rg * 16 + g, r1l = r0l + 8;
    const int gi0 = rb + r0l, gi1 = rb + r1l;
    const __half2 sl2_0 = __float2half2_rn(ssl[r0l]);
    const __half2 sl2_1 = __float2half2_rn(ssl[r1l]);
    const __half2 nm2_0 = __float2half2_rn(-sMx[r0l]);
    const __half2 nm2_1 = __float2half2_rn(-sMx[r1l]);
    const uint4* WhT4 = reinterpret_cast<const uint4*>(WhT2);
    const uint32_t ob = (lane < 4) ? 0x3C003C00u : 0u;   // ones B column

    // ldmatrix base addresses (buffer 0), per nt-pair p
    uint32_t ldsm_base[4];
    {
        uint32_t swh_addr = (uint32_t)__cvta_generic_to_shared(dyn);
#pragma unroll
        for (int p = 0; p < 4; p++) {
            int rowp = nbase + p * 16 + (lane & 7) + (((lane >> 4) & 1) << 3);
            ldsm_base[p] = swh_addr + rowp * (S * 4) + (((lane >> 3) & 1) << 4);
        }
    }

    float acc[9][4];
#pragma unroll
    for (int nt = 0; nt < 9; nt++)
#pragma unroll
        for (int v = 0; v < 4; v++) acc[nt][v] = 0.f;

    uint2 nm0, nm1;
    uint4 wh[4];

    // ---- prologue: tile 0 frags + fill ----
    {
        nm0 = *reinterpret_cast<const uint2*>(Amask + (size_t)gi0 * (NN / 32));
        nm1 = *reinterpret_cast<const uint2*>(Amask + (size_t)gi1 * (NN / 32));
#pragma unroll
        for (int i = 0; i < 4; i++) {
            int flat = t + i * 256;
            int d = flat >> 3, jw = flat & 7;
            wh[i] = WhT4[(size_t)(h * DK + d) * (NN / 8) + jw];
        }
        uint64_t M0 = merge_mask(nm0, gi0, 0);
        uint64_t M1 = merge_mask(nm1, gi1, 0);
#pragma unroll
        for (int q = 0; q < 2; q++) {
            int kc = 2 * ch + q;
            int c0 = kc * 16 + 2 * tig;
            __half2 srA = *reinterpret_cast<const __half2*>(ssr + c0);
            __half2 srB = *reinterpret_cast<const __half2*>(ssr + c0 + 8);
            uint32_t s0 = (uint32_t)(M0 >> c0);
            uint32_t s1 = (uint32_t)(M1 >> c0);
            uint4 v;
            v.x = wcalc(sl2_0, nm2_0, srA, s0 & 1u, s0 & 2u);
            v.y = wcalc(sl2_1, nm2_1, srA, s1 & 1u, s1 & 2u);
            v.z = wcalc(sl2_0, nm2_0, srB, (s0 >> 8) & 1u, (s0 >> 8) & 2u);
            v.w = wcalc(sl2_1, nm2_1, srB, (s1 >> 8) & 1u, (s1 >> 8) & 2u);
            *reinterpret_cast<uint4*>(sfrag + ((rg * 4 + kc) * 32 + lane) * 4) = v;
        }
#pragma unroll
        for (int i = 0; i < 4; i++) {
            int flat = t + i * 256;
            int d = flat >> 3, jw = flat & 7;
            *reinterpret_cast<uint4*>(dyn + d * S + jw * 4) = wh[i];
        }
    }
    __syncthreads();

    for (int jt = 0; jt < NN / KT; jt++) {
        // ---- prefetch globals for jt+1 ----
        if (jt + 1 < NN / KT) {
            const int jbn = (jt + 1) * KT;
            nm0 = *reinterpret_cast<const uint2*>(Amask + (size_t)gi0 * (NN / 32) + 2 * (jt + 1));
            nm1 = *reinterpret_cast<const uint2*>(Amask + (size_t)gi1 * (NN / 32) + 2 * (jt + 1));
#pragma unroll
            for (int i = 0; i < 4; i++) {
                int flat = t + i * 256;
                int d = flat >> 3, jw = flat & 7;
                wh[i] = WhT4[(size_t)(h * DK + d) * (NN / 8) + (jbn >> 3) + jw];
            }
        }

        // ---- MMA phase (buffer jt&1) ----
        {
            const uint32_t* fsrc = sfrag + ((jt & 1) ? FRAG_W : 0);
            const uint32_t bo = (jt & 1) ? WH_BYTES : 0;
#pragma unroll
            for (int kc = 0; kc < 4; kc++) {
                uint4 av = *reinterpret_cast<const uint4*>(fsrc + ((rg * 4 + kc) * 32 + lane) * 4);
#pragma unroll
                for (int p = 0; p < 4; p++) {
                    uint32_t b0, b1, b2, b3;
                    ldsm4(b0, b1, b2, b3, ldsm_base[p] + bo + kc * 32);
                    mma16816(acc[2 * p], av.x, av.y, av.z, av.w, b0, b1);
                    mma16816(acc[2 * p + 1], av.x, av.y, av.z, av.w, b2, b3);
                }
                mma16816(acc[8], av.x, av.y, av.z, av.w, ob, ob);
            }
        }

        // ---- frags + fill for jt+1 (buffer (jt+1)&1) ----
        if (jt + 1 < NN / KT) {
            const int jbn = (jt + 1) * KT;
            uint64_t M0 = merge_mask(nm0, gi0, jbn);
            uint64_t M1 = merge_mask(nm1, gi1, jbn);
            uint32_t* fdst = sfrag + (((jt + 1) & 1) ? FRAG_W : 0);
#pragma unroll
            for (int q = 0; q < 2; q++) {
                int kc = 2 * ch + q;
                int c0 = kc * 16 + 2 * tig;
                __half2 srA = *reinterpret_cast<const __half2*>(ssr + jbn + c0);
                __half2 srB = *reinterpret_cast<const __half2*>(ssr + jbn + c0 + 8);
                uint32_t s0 = (uint32_t)(M0 >> c0);
                uint32_t s1 = (uint32_t)(M1 >> c0);
                uint4 v;
                v.x = wcalc(sl2_0, nm2_0, srA, s0 & 1u, s0 & 2u);
                v.y = wcalc(sl2_1, nm2_1, srA, s1 & 1u, s1 & 2u);
                v.z = wcalc(sl2_0, nm2_0, srB, (s0 >> 8) & 1u, (s0 >> 8) & 2u);
                v.w = wcalc(sl2_1, nm2_1, srB, (s1 >> 8) & 1u, (s1 >> 8) & 2u);
                *reinterpret_cast<uint4*>(fdst + ((rg * 4 + kc) * 32 + lane) * 4) = v;
            }
            uint32_t* swh = dyn + (((jt + 1) & 1) ? WH_W : 0);
#pragma unroll
            for (int i = 0; i < 4; i++) {
                int flat = t + i * 256;
                int d = flat >> 3, jw = flat & 7;
                *reinterpret_cast<uint4*>(swh + d * S + jw * 4) = wh[i];
            }
        }
        __syncthreads();
    }

    // ---- lsum from ones-column MMA: quad-leader holds col 0 ----
    float ls0 = __shfl_sync(0xFFFFFFFFu, acc[8][0], lane & ~3);
    float ls1 = __shfl_sync(0xFFFFFFFFu, acc[8][2], lane & ~3);
    const float inv0 = 1.f / ls0;
    const float inv1 = 1.f / ls1;

    // ---- epilogue: normalize + ELU, float2 stores ----
    const int row0 = rb + r0l, row1 = rb + r1l;
#pragma unroll
    for (int nt = 0; nt < 8; nt++) {
        int col = h * DK + nbase + nt * 8 + 2 * tig;
        float x0 = acc[nt][0] * inv0, x1 = acc[nt][1] * inv0;
        float y0 = acc[nt][2] * inv1, y1 = acc[nt][3] * inv1;
        float2 o0, o1;
        o0.x = x0 > 0.f ? x0 : (__expf(x0) - 1.f);
        o0.y = x1 > 0.f ? x1 : (__expf(x1) - 1.f);
        o1.x = y0 > 0.f ? y0 : (__expf(y0) - 1.f);
        o1.y = y1 > 0.f ? y1 : (__expf(y1) - 1.f);
        *reinterpret_cast<float2*>(&out[(size_t)row0 * OUT_DIM + col]) = o0;
        *reinterpret_cast<float2*>(&out[(size_t)row1 * OUT_DIM + col]) = o1;
    }
}

// ---------------- launch ----------------
extern "C" void kernel_launch(void* const* d_in, const int* in_sizes, int n_in,
                              void* d_out, int out_size) {
    const float* H  = (const float*)d_in[0];
    const int*   A  = (const int*)  d_in[1];
    const float* W  = (const float*)d_in[2];
    const float* al = (const float*)d_in[3];
    const float* ar = (const float*)d_in[4];
    float* out = (float*)d_out;

    float*    Wh;    cudaGetSymbolAddress((void**)&Wh,    g_Wh);
    __half*   WhT2;  cudaGetSymbolAddress((void**)&WhT2,  g_WhT2);
    uint32_t* Amask; cudaGetSymbolAddress((void**)&Amask, g_Amask);
    float*    slT;   cudaGetSymbolAddress((void**)&slT,   g_slT);
    float*    srT;   cudaGetSymbolAddress((void**)&srT,   g_srT);
    __half*   srT2;  cudaGetSymbolAddress((void**)&srT2,  g_srT2);
    float*    MT;    cudaGetSymbolAddress((void**)&MT,    g_MT);

    dim3 gA(OUT_DIM / 64, NN / 128);
    gemm_kernel<<<gA, 256>>>(H, W, Wh, WhT2);

    score_kernel<<<NN, 128>>>(Wh, al, ar, slT, srT, srT2);

    rowmax_kernel<<<NN, 256>>>(A, slT, srT, MT, Amask);

    const int dyn_bytes = 2 * WH_BYTES;   // 36864
    cudaFuncSetAttribute(attn_kernel, cudaFuncAttributeMaxDynamicSharedMemorySize, dyn_bytes);
    dim3 gC(NN / 64, HEADS);
    attn_kernel<<<gC, 256, dyn_bytes>>>(Amask, WhT2, slT, srT2, MT, out);
}

// round 11
// speedup vs baseline: 3.2278x; 1.2925x over previous
#include <cuda_runtime.h>
#include <cuda_fp16.h>
#include <math.h>
#include <stdint.h>

#define NN 4096
#define IN_DIM 512
#define OUT_DIM 512
#define HEADS 4
#define DK 128
#define KT 64
#define S 36                       // swh row stride (words) = 144B
#define WH_W (128 * S)
#define WH_BYTES (WH_W * 4)
#define FRAG_W (16 * 32 * 4)
#define LOG2E 1.4426950408889634f

// gemm smem geometry
#define GA_S 36                    // sA [m][k] stride (words)
#define GB_S 132                   // sB [k][n] stride (words)
#define GA_W (128 * GA_S)          // 4608
#define GB_W (32 * GB_S)           // 4224
#define GBUF_W (GA_W + GB_W)       // 8832

// ---------------- scratch ----------------
__device__ float    g_Wh[NN * OUT_DIM];
__device__ __half   g_WhT2[OUT_DIM * NN];     // [d'][j] fp16
__device__ uint32_t g_Amask[NN * (NN / 32)];
__device__ float    g_slT[HEADS * NN];        // *LOG2E
__device__ float    g_srT[HEADS * NN];        // *LOG2E fp32
__device__ __half   g_srT2[HEADS * NN];       // *LOG2E fp16
__device__ float    g_MT[HEADS * NN];

__device__ __forceinline__ float lrelu(float x) { return fmaxf(x, 0.2f * x); }
__device__ __forceinline__ float tf32r(float v) {
    uint32_t r;
    asm("cvt.rn.tf32.f32 %0, %1;" : "=r"(r) : "f"(v));
    return __uint_as_float(r);
}
__device__ __forceinline__ void mma_tf32(float* c, uint32_t a0, uint32_t a1,
                                         uint32_t a2, uint32_t a3,
                                         uint32_t b0, uint32_t b1) {
    asm volatile(
        "mma.sync.aligned.m16n8k8.row.col.f32.tf32.tf32.f32 "
        "{%0,%1,%2,%3}, {%4,%5,%6,%7}, {%8,%9}, {%0,%1,%2,%3};"
        : "+f"(c[0]), "+f"(c[1]), "+f"(c[2]), "+f"(c[3])
        : "r"(a0), "r"(a1), "r"(a2), "r"(a3), "r"(b0), "r"(b1));
}
__device__ __forceinline__ void mma16816(float* c, uint32_t a0, uint32_t a1,
                                         uint32_t a2, uint32_t a3,
                                         uint32_t b0, uint32_t b1) {
    asm volatile(
        "mma.sync.aligned.m16n8k16.row.col.f32.f16.f16.f32 "
        "{%0,%1,%2,%3}, {%4,%5,%6,%7}, {%8,%9}, {%0,%1,%2,%3};"
        : "+f"(c[0]), "+f"(c[1]), "+f"(c[2]), "+f"(c[3])
        : "r"(a0), "r"(a1), "r"(a2), "r"(a3), "r"(b0), "r"(b1));
}
__device__ __forceinline__ void ldsm4(uint32_t& r0, uint32_t& r1,
                                      uint32_t& r2, uint32_t& r3, uint32_t addr) {
    asm volatile("ldmatrix.sync.aligned.m8n8.x4.shared.b16 {%0,%1,%2,%3}, [%4];"
                 : "=r"(r0), "=r"(r1), "=r"(r2), "=r"(r3) : "r"(addr));
}
__device__ __forceinline__ uint64_t merge_mask(uint2 m, int gi, int jb) {
    uint64_t M = (uint64_t)m.x | ((uint64_t)m.y << 32);
    unsigned sc = (unsigned)(gi - jb);
    if (sc < 64u) M |= (1ull << sc);
    return M;
}
__device__ __forceinline__ uint32_t wcalc(__half2 sl2, __half2 nm2, __half2 sr2,
                                          uint32_t b0, uint32_t b1) {
    __half2 e = __hadd2(sl2, sr2);
    __half2 t = __hmul2(e, __float2half2_rn(0.2f));
    e = __hmax2(e, t);
    e = __hadd2(e, nm2);
    __half2 w = h2exp2(e);
    uint32_t m = (b0 ? 0x3C00u : 0u) | (b1 ? 0x3C000000u : 0u);
    __half2 mh = *reinterpret_cast<__half2*>(&m);
    w = __hmul2(w, mh);
    return *reinterpret_cast<uint32_t*>(&w);
}

// ---------------- Kernel A: Wh = H @ W via tf32 MMA -------------------------
// grid (4, 32), 256 threads (8 warps). CTA = 128m x 128n, warp = 32m x 64n.
// k staged 32, double-buffered. Epilogue: Wh fp32 + WhT2 fp16 (scattered).
__global__ void __launch_bounds__(256) gemm_kernel(const float* __restrict__ H,
                                                   const float* __restrict__ W,
                                                   float* __restrict__ Wh,
                                                   __half* __restrict__ WhT2) {
    extern __shared__ float gs[];
    const int t = threadIdx.x;
    const int wid = t >> 5, lane = t & 31;
    const int g = lane >> 2, tig = lane & 3;
    const int wm = wid & 3, wn = wid >> 2;
    const int rb = blockIdx.y * 128, cb = blockIdx.x * 128;

    float acc[2][8][4];
#pragma unroll
    for (int mt = 0; mt < 2; mt++)
#pragma unroll
        for (int nt = 0; nt < 8; nt++)
#pragma unroll
            for (int v = 0; v < 4; v++) acc[mt][nt][v] = 0.f;

    // fill mappings
    // A: flat4 = t + i*256 (i<4): m = flat4>>3, k4 = flat4&7
    // B: flat4 = t + i*256 (i<4): k = flat4>>5, n4 = flat4&31
    float4 ha[4], wb[4];

    // prologue: stage 0
#pragma unroll
    for (int i = 0; i < 4; i++) {
        int f = t + i * 256;
        ha[i] = *reinterpret_cast<const float4*>(&H[(size_t)(rb + (f >> 3)) * IN_DIM + (f & 7) * 4]);
        wb[i] = *reinterpret_cast<const float4*>(&W[(size_t)(f >> 5) * OUT_DIM + cb + (f & 31) * 4]);
    }
    {
        float* sA = gs;
        float* sB = gs + GA_W;
#pragma unroll
        for (int i = 0; i < 4; i++) {
            int f = t + i * 256;
            float4 a = make_float4(tf32r(ha[i].x), tf32r(ha[i].y), tf32r(ha[i].z), tf32r(ha[i].w));
            float4 b = make_float4(tf32r(wb[i].x), tf32r(wb[i].y), tf32r(wb[i].z), tf32r(wb[i].w));
            *reinterpret_cast<float4*>(sA + (f >> 3) * GA_S + (f & 7) * 4) = a;
            *reinterpret_cast<float4*>(sB + (f >> 5) * GB_S + (f & 31) * 4) = b;
        }
    }
    __syncthreads();

    const int am0 = (wm * 32 + g) * GA_S;        // mt=0 row g
    const int am1 = am0 + 8 * GA_S;              // row g+8
    const int bn = wn * 64 + g;

    for (int st = 0; st < IN_DIM / 32; st++) {
        // prefetch next stage
        if (st + 1 < IN_DIM / 32) {
            int kb = (st + 1) * 32;
#pragma unroll
            for (int i = 0; i < 4; i++) {
                int f = t + i * 256;
                ha[i] = *reinterpret_cast<const float4*>(
                    &H[(size_t)(rb + (f >> 3)) * IN_DIM + kb + (f & 7) * 4]);
                wb[i] = *reinterpret_cast<const float4*>(
                    &W[(size_t)(kb + (f >> 5)) * OUT_DIM + cb + (f & 31) * 4]);
            }
        }
        // mma on buffer st&1
        {
            const float* sA = gs + (st & 1) * GBUF_W;
            const float* sB = sA + GA_W;
#pragma unroll
            for (int ks = 0; ks < 4; ks++) {
                const int k0 = ks * 8 + tig;
                uint32_t a00 = __float_as_uint(sA[am0 + k0]);
                uint32_t a01 = __float_as_uint(sA[am1 + k0]);
                uint32_t a02 = __float_as_uint(sA[am0 + k0 + 4]);
                uint32_t a03 = __float_as_uint(sA[am1 + k0 + 4]);
                uint32_t a10 = __float_as_uint(sA[am0 + 16 * GA_S + k0]);
                uint32_t a11 = __float_as_uint(sA[am1 + 16 * GA_S + k0]);
                uint32_t a12 = __float_as_uint(sA[am0 + 16 * GA_S + k0 + 4]);
                uint32_t a13 = __float_as_uint(sA[am1 + 16 * GA_S + k0 + 4]);
#pragma unroll
                for (int nt = 0; nt < 8; nt++) {
                    uint32_t b0 = __float_as_uint(sB[k0 * GB_S + bn + nt * 8]);
                    uint32_t b1 = __float_as_uint(sB[(k0 + 4) * GB_S + bn + nt * 8]);
                    mma_tf32(acc[0][nt], a00, a01, a02, a03, b0, b1);
                    mma_tf32(acc[1][nt], a10, a11, a12, a13, b0, b1);
                }
            }
        }
        // store next stage
        if (st + 1 < IN_DIM / 32) {
            float* sA = gs + ((st + 1) & 1) * GBUF_W;
            float* sB = sA + GA_W;
#pragma unroll
            for (int i = 0; i < 4; i++) {
                int f = t + i * 256;
                float4 a = make_float4(tf32r(ha[i].x), tf32r(ha[i].y), tf32r(ha[i].z), tf32r(ha[i].w));
                float4 b = make_float4(tf32r(wb[i].x), tf32r(wb[i].y), tf32r(wb[i].z), tf32r(wb[i].w));
                *reinterpret_cast<float4*>(sA + (f >> 3) * GA_S + (f & 7) * 4) = a;
                *reinterpret_cast<float4*>(sB + (f >> 5) * GB_S + (f & 31) * 4) = b;
            }
        }
        __syncthreads();
    }

    // epilogue
#pragma unroll
    for (int mt = 0; mt < 2; mt++) {
        int row = rb + wm * 32 + mt * 16 + g;
#pragma unroll
        for (int nt = 0; nt < 8; nt++) {
            int col = cb + wn * 64 + nt * 8 + 2 * tig;
            float c0 = acc[mt][nt][0], c1 = acc[mt][nt][1];
            float c2 = acc[mt][nt][2], c3 = acc[mt][nt][3];
            *reinterpret_cast<float2*>(&Wh[(size_t)row * OUT_DIM + col]) = make_float2(c0, c1);
            *reinterpret_cast<float2*>(&Wh[(size_t)(row + 8) * OUT_DIM + col]) = make_float2(c2, c3);
            WhT2[(size_t)col * NN + row]           = __float2half_rn(c0);
            WhT2[(size_t)(col + 1) * NN + row]     = __float2half_rn(c1);
            WhT2[(size_t)col * NN + row + 8]       = __float2half_rn(c2);
            WhT2[(size_t)(col + 1) * NN + row + 8] = __float2half_rn(c3);
        }
    }
}

// ---------------- Kernel B: sl/sr, prescaled; fp32 + fp16 copies ------------
__global__ void score_kernel(const float* __restrict__ Wh,
                             const float* __restrict__ al,
                             const float* __restrict__ ar,
                             float* __restrict__ slT, float* __restrict__ srT,
                             __half* __restrict__ srT2) {
    int i = blockIdx.x;
    int h = threadIdx.x >> 5;
    int lane = threadIdx.x & 31;
    float4 w = *reinterpret_cast<const float4*>(&Wh[(size_t)i * OUT_DIM + h * DK + lane * 4]);
    float4 l = *reinterpret_cast<const float4*>(&al[h * DK + lane * 4]);
    float4 r = *reinterpret_cast<const float4*>(&ar[h * DK + lane * 4]);
    float s1 = w.x * l.x + w.y * l.y + w.z * l.z + w.w * l.w;
    float s2 = w.x * r.x + w.y * r.y + w.z * r.z + w.w * r.w;
#pragma unroll
    for (int off = 16; off > 0; off >>= 1) {
        s1 += __shfl_xor_sync(0xFFFFFFFFu, s1, off);
        s2 += __shfl_xor_sync(0xFFFFFFFFu, s2, off);
    }
    if (lane == 0) {
        slT[h * NN + i] = s1 * LOG2E;
        srT[h * NN + i] = s2 * LOG2E;
        srT2[h * NN + i] = __float2half_rn(s2 * LOG2E);
    }
}

// ---------------- Kernel B2: branch-free masked row-max + bitmask -----------
__global__ void __launch_bounds__(256) rowmax_kernel(const int* __restrict__ A,
                                                     const float* __restrict__ slT,
                                                     const float* __restrict__ srT,
                                                     float* __restrict__ MT,
                                                     uint32_t* __restrict__ Amask) {
    int i = blockIdx.x;
    int t = threadIdx.x;
    int w = t >> 5, lane = t & 31;
    const int* arow = A + (size_t)i * NN;
    float mx[HEADS];
#pragma unroll
    for (int h = 0; h < HEADS; h++) mx[h] = -INFINITY;
#pragma unroll 4
    for (int it = 0; it < NN / 256; it++) {
        int j = it * 256 + t;
        bool edge = arow[j] > 0;
        uint32_t bits = __ballot_sync(0xFFFFFFFFu, edge);
        if (lane == 0) Amask[i * (NN / 32) + it * 8 + w] = bits;
        float sel = (edge || (j == i)) ? 0.f : -INFINITY;   // additive mask
#pragma unroll
        for (int h = 0; h < HEADS; h++)
            mx[h] = fmaxf(mx[h], srT[h * NN + j] + sel);
    }
    __shared__ float red[HEADS][256];
#pragma unroll
    for (int h = 0; h < HEADS; h++) red[h][t] = mx[h];
    __syncthreads();
    for (int s = 128; s > 0; s >>= 1) {
        if (t < s) {
#pragma unroll
            for (int h = 0; h < HEADS; h++)
                red[h][t] = fmaxf(red[h][t], red[h][t + s]);
        }
        __syncthreads();
    }
    if (t < HEADS) {
        float e = slT[t * NN + i] + red[t][0];
        MT[t * NN + i] = lrelu(e);
    }
}

// ---------------- Kernel C: fp16 MMA attn (unchanged from R10) --------------
__global__ void __launch_bounds__(256, 2) attn_kernel(const uint32_t* __restrict__ Amask,
                                                      const __half* __restrict__ WhT2,
                                                      const float* __restrict__ slT,
                                                      const __half* __restrict__ srT2,
                                                      const float* __restrict__ MT,
                                                      float* __restrict__ out) {
    extern __shared__ uint32_t dyn[];
    __shared__ __align__(16) __half ssr[NN];
    __shared__ __align__(16) uint32_t sfrag[2 * FRAG_W];
    __shared__ float ssl[64], sMx[64];

    const int h = blockIdx.y;
    const int rb = blockIdx.x * 64;
    const int t = threadIdx.x;
    const int wid = t >> 5, lane = t & 31;
    const int g = lane >> 2, tig = lane & 3;
    const int rg = wid >> 1;
    const int ch = wid & 1;
    const int nbase = ch * 64;

    {
        const uint4* s4 = reinterpret_cast<const uint4*>(srT2 + (size_t)h * NN);
#pragma unroll
        for (int i = 0; i < 2; i++) {
            int idx = t + i * 256;
            reinterpret_cast<uint4*>(ssr)[idx] = s4[idx];
        }
    }
    if (t < 64) {
        ssl[t] = slT[h * NN + rb + t];
        sMx[t] = MT[h * NN + rb + t];
    }
    __syncthreads();

    const int r0l = rg * 16 + g, r1l = r0l + 8;
    const int gi0 = rb + r0l, gi1 = rb + r1l;
    const __half2 sl2_0 = __float2half2_rn(ssl[r0l]);
    const __half2 sl2_1 = __float2half2_rn(ssl[r1l]);
    const __half2 nm2_0 = __float2half2_rn(-sMx[r0l]);
    const __half2 nm2_1 = __float2half2_rn(-sMx[r1l]);
    const uint4* WhT4 = reinterpret_cast<const uint4*>(WhT2);
    const uint32_t ob = (lane < 4) ? 0x3C003C00u : 0u;

    uint32_t ldsm_base[4];
    {
        uint32_t swh_addr = (uint32_t)__cvta_generic_to_shared(dyn);
#pragma unroll
        for (int p = 0; p < 4; p++) {
            int rowp = nbase + p * 16 + (lane & 7) + (((lane >> 4) & 1) << 3);
            ldsm_base[p] = swh_addr + rowp * (S * 4) + (((lane >> 3) & 1) << 4);
        }
    }

    float acc[9][4];
#pragma unroll
    for (int nt = 0; nt < 9; nt++)
#pragma unroll
        for (int v = 0; v < 4; v++) acc[nt][v] = 0.f;

    uint2 nm0, nm1;
    uint4 wh[4];

    {
        nm0 = *reinterpret_cast<const uint2*>(Amask + (size_t)gi0 * (NN / 32));
        nm1 = *reinterpret_cast<const uint2*>(Amask + (size_t)gi1 * (NN / 32));
#pragma unroll
        for (int i = 0; i < 4; i++) {
            int flat = t + i * 256;
            int d = flat >> 3, jw = flat & 7;
            wh[i] = WhT4[(size_t)(h * DK + d) * (NN / 8) + jw];
        }
        uint64_t M0 = merge_mask(nm0, gi0, 0);
        uint64_t M1 = merge_mask(nm1, gi1, 0);
#pragma unroll
        for (int q = 0; q < 2; q++) {
            int kc = 2 * ch + q;
            int c0 = kc * 16 + 2 * tig;
            __half2 srA = *reinterpret_cast<const __half2*>(ssr + c0);
            __half2 srB = *reinterpret_cast<const __half2*>(ssr + c0 + 8);
            uint32_t s0 = (uint32_t)(M0 >> c0);
            uint32_t s1 = (uint32_t)(M1 >> c0);
            uint4 v;
            v.x = wcalc(sl2_0, nm2_0, srA, s0 & 1u, s0 & 2u);
            v.y = wcalc(sl2_1, nm2_1, srA, s1 & 1u, s1 & 2u);
            v.z = wcalc(sl2_0, nm2_0, srB, (s0 >> 8) & 1u, (s0 >> 8) & 2u);
            v.w = wcalc(sl2_1, nm2_1, srB, (s1 >> 8) & 1u, (s1 >> 8) & 2u);
            *reinterpret_cast<uint4*>(sfrag + ((rg * 4 + kc) * 32 + lane) * 4) = v;
        }
#pragma unroll
        for (int i = 0; i < 4; i++) {
            int flat = t + i * 256;
            int d = flat >> 3, jw = flat & 7;
            *reinterpret_cast<uint4*>(dyn + d * S + jw * 4) = wh[i];
        }
    }
    __syncthreads();

    for (int jt = 0; jt < NN / KT; jt++) {
        if (jt + 1 < NN / KT) {
            const int jbn = (jt + 1) * KT;
            nm0 = *reinterpret_cast<const uint2*>(Amask + (size_t)gi0 * (NN / 32) + 2 * (jt + 1));
            nm1 = *reinterpret_cast<const uint2*>(Amask + (size_t)gi1 * (NN / 32) + 2 * (jt + 1));
#pragma unroll
            for (int i = 0; i < 4; i++) {
                int flat = t + i * 256;
                int d = flat >> 3, jw = flat & 7;
                wh[i] = WhT4[(size_t)(h * DK + d) * (NN / 8) + (jbn >> 3) + jw];
            }
        }
        {
            const uint32_t* fsrc = sfrag + ((jt & 1) ? FRAG_W : 0);
            const uint32_t bo = (jt & 1) ? WH_BYTES : 0;
#pragma unroll
            for (int kc = 0; kc < 4; kc++) {
                uint4 av = *reinterpret_cast<const uint4*>(fsrc + ((rg * 4 + kc) * 32 + lane) * 4);
#pragma unroll
                for (int p = 0; p < 4; p++) {
                    uint32_t b0, b1, b2, b3;
                    ldsm4(b0, b1, b2, b3, ldsm_base[p] + bo + kc * 32);
                    mma16816(acc[2 * p], av.x, av.y, av.z, av.w, b0, b1);
                    mma16816(acc[2 * p + 1], av.x, av.y, av.z, av.w, b2, b3);
                }
                mma16816(acc[8], av.x, av.y, av.z, av.w, ob, ob);
            }
        }
        if (jt + 1 < NN / KT) {
            const int jbn = (jt + 1) * KT;
            uint64_t M0 = merge_mask(nm0, gi0, jbn);
            uint64_t M1 = merge_mask(nm1, gi1, jbn);
            uint32_t* fdst = sfrag + (((jt + 1) & 1) ? FRAG_W : 0);
#pragma unroll
            for (int q = 0; q < 2; q++) {
                int kc = 2 * ch + q;
                int c0 = kc * 16 + 2 * tig;
                __half2 srA = *reinterpret_cast<const __half2*>(ssr + jbn + c0);
                __half2 srB = *reinterpret_cast<const __half2*>(ssr + jbn + c0 + 8);
                uint32_t s0 = (uint32_t)(M0 >> c0);
                uint32_t s1 = (uint32_t)(M1 >> c0);
                uint4 v;
                v.x = wcalc(sl2_0, nm2_0, srA, s0 & 1u, s0 & 2u);
                v.y = wcalc(sl2_1, nm2_1, srA, s1 & 1u, s1 & 2u);
                v.z = wcalc(sl2_0, nm2_0, srB, (s0 >> 8) & 1u, (s0 >> 8) & 2u);
                v.w = wcalc(sl2_1, nm2_1, srB, (s1 >> 8) & 1u, (s1 >> 8) & 2u);
                *reinterpret_cast<uint4*>(fdst + ((rg * 4 + kc) * 32 + lane) * 4) = v;
            }
            uint32_t* swh = dyn + (((jt + 1) & 1) ? WH_W : 0);
#pragma unroll
            for (int i = 0; i < 4; i++) {
                int flat = t + i * 256;
                int d = flat >> 3, jw = flat & 7;
                *reinterpret_cast<uint4*>(swh + d * S + jw * 4) = wh[i];
            }
        }
        __syncthreads();
    }

    float ls0 = __shfl_sync(0xFFFFFFFFu, acc[8][0], lane & ~3);
    float ls1 = __shfl_sync(0xFFFFFFFFu, acc[8][2], lane & ~3);
    const float inv0 = 1.f / ls0;
    const float inv1 = 1.f / ls1;

    const int row0 = rb + r0l, row1 = rb + r1l;
#pragma unroll
    for (int nt = 0; nt < 8; nt++) {
        int col = h * DK + nbase + nt * 8 + 2 * tig;
        float x0 = acc[nt][0] * inv0, x1 = acc[nt][1] * inv0;
        float y0 = acc[nt][2] * inv1, y1 = acc[nt][3] * inv1;
        float2 o0, o1;
        o0.x = x0 > 0.f ? x0 : (__expf(x0) - 1.f);
        o0.y = x1 > 0.f ? x1 : (__expf(x1) - 1.f);
        o1.x = y0 > 0.f ? y0 : (__expf(y0) - 1.f);
        o1.y = y1 > 0.f ? y1 : (__expf(y1) - 1.f);
        *reinterpret_cast<float2*>(&out[(size_t)row0 * OUT_DIM + col]) = o0;
        *reinterpret_cast<float2*>(&out[(size_t)row1 * OUT_DIM + col]) = o1;
    }
}

// ---------------- launch ----------------
extern "C" void kernel_launch(void* const* d_in, const int* in_sizes, int n_in,
                              void* d_out, int out_size) {
    const float* H  = (const float*)d_in[0];
    const int*   A  = (const int*)  d_in[1];
    const float* W  = (const float*)d_in[2];
    const float* al = (const float*)d_in[3];
    const float* ar = (const float*)d_in[4];
    float* out = (float*)d_out;

    float*    Wh;    cudaGetSymbolAddress((void**)&Wh,    g_Wh);
    __half*   WhT2;  cudaGetSymbolAddress((void**)&WhT2,  g_WhT2);
    uint32_t* Amask; cudaGetSymbolAddress((void**)&Amask, g_Amask);
    float*    slT;   cudaGetSymbolAddress((void**)&slT,   g_slT);
    float*    srT;   cudaGetSymbolAddress((void**)&srT,   g_srT);
    __half*   srT2;  cudaGetSymbolAddress((void**)&srT2,  g_srT2);
    float*    MT;    cudaGetSymbolAddress((void**)&MT,    g_MT);

    const int gemm_smem = 2 * GBUF_W * 4;   // 70656
    cudaFuncSetAttribute(gemm_kernel, cudaFuncAttributeMaxDynamicSharedMemorySize, gemm_smem);
    dim3 gA(OUT_DIM / 128, NN / 128);
    gemm_kernel<<<gA, 256, gemm_smem>>>(H, W, Wh, WhT2);

    score_kernel<<<NN, 128>>>(Wh, al, ar, slT, srT, srT2);

    rowmax_kernel<<<NN, 256>>>(A, slT, srT, MT, Amask);

    const int dyn_bytes = 2 * WH_BYTES;   // 36864
    cudaFuncSetAttribute(attn_kernel, cudaFuncAttributeMaxDynamicSharedMemorySize, dyn_bytes);
    dim3 gC(NN / 64, HEADS);
    attn_kernel<<<gC, 256, dyn_bytes>>>(Amask, WhT2, slT, srT2, MT, out);
}